// round 1
// baseline (speedup 1.0000x reference)
#include <cuda_runtime.h>

#define S_LEN 4096
#define B_SZ  2
#define DM    512
#define HN    8
#define DH    64

typedef unsigned long long ull;

// ---------------- packed f32x2 helpers (PTX-only on Blackwell) ----------------
__device__ __forceinline__ void ffma2(ull& d, ull a, ull b) {
    asm("fma.rn.f32x2 %0, %1, %2, %0;" : "+l"(d) : "l"(a), "l"(b));
}
__device__ __forceinline__ ull fmul2(ull a, ull b) {
    ull r; asm("mul.rn.f32x2 %0, %1, %2;" : "=l"(r) : "l"(a), "l"(b)); return r;
}
__device__ __forceinline__ ull pack2(float x, float y) {
    ull r; asm("mov.b64 %0, {%1, %2};" : "=l"(r) : "f"(x), "f"(y)); return r;
}
__device__ __forceinline__ void unpack2(ull v, float& x, float& y) {
    asm("mov.b64 {%0, %1}, %2;" : "=f"(x), "=f"(y) : "l"(v));
}

// ---------------- scratch (no cudaMalloc allowed) ----------------
__device__ float g_q[(size_t)B_SZ * S_LEN * DM];
__device__ float g_k[(size_t)B_SZ * S_LEN * DM];
__device__ float g_v[(size_t)B_SZ * S_LEN * DM];
__device__ float g_ctx[(size_t)B_SZ * S_LEN * DM];

// =====================================================================
// GEMM: C[m][n] = sum_k A[m][k] * W[n][k] + bias[n]
// M = 8192 (B*S), N = K = 512. Tile 64x64, BK=32, 256 threads, 4x4/thread
// A rows stored DUPLICATED in smem so LDS.128 yields two (a,a) f32x2 pairs.
// =====================================================================
__global__ void __launch_bounds__(256) gemm_bias_kernel(
    const float* __restrict__ A, const float* __restrict__ W,
    const float* __restrict__ bias, float* __restrict__ C)
{
    __shared__ __align__(16) float As[32][128];  // [k][2*r] duplicated pairs
    __shared__ __align__(16) float Ws[32][64];   // [k][n]

    const int tid = threadIdx.x;
    const int tx = tid & 15, ty = tid >> 4;
    const int m0 = blockIdx.x * 64;
    const int n0 = blockIdx.y * 64;

    ull acc[4][2];
    #pragma unroll
    for (int i = 0; i < 4; i++) { acc[i][0] = 0ull; acc[i][1] = 0ull; }

    for (int k0 = 0; k0 < DM; k0 += 32) {
        #pragma unroll
        for (int e = tid; e < 512; e += 256) {
            int r = e >> 3, k4 = (e & 7) << 2;
            float4 v = *reinterpret_cast<const float4*>(&A[(size_t)(m0 + r) * DM + k0 + k4]);
            As[k4 + 0][2 * r] = v.x; As[k4 + 0][2 * r + 1] = v.x;
            As[k4 + 1][2 * r] = v.y; As[k4 + 1][2 * r + 1] = v.y;
            As[k4 + 2][2 * r] = v.z; As[k4 + 2][2 * r + 1] = v.z;
            As[k4 + 3][2 * r] = v.w; As[k4 + 3][2 * r + 1] = v.w;
        }
        #pragma unroll
        for (int e = tid; e < 512; e += 256) {
            int n = e >> 3, k4 = (e & 7) << 2;
            float4 v = *reinterpret_cast<const float4*>(&W[(size_t)(n0 + n) * DM + k0 + k4]);
            Ws[k4 + 0][n] = v.x; Ws[k4 + 1][n] = v.y;
            Ws[k4 + 2][n] = v.z; Ws[k4 + 3][n] = v.w;
        }
        __syncthreads();
        #pragma unroll 8
        for (int k = 0; k < 32; k++) {
            ulonglong2 a01 = *reinterpret_cast<const ulonglong2*>(&As[k][ty * 8]);      // (r0,r0)(r1,r1)
            ulonglong2 a23 = *reinterpret_cast<const ulonglong2*>(&As[k][ty * 8 + 4]);  // (r2,r2)(r3,r3)
            ulonglong2 w   = *reinterpret_cast<const ulonglong2*>(&Ws[k][tx * 4]);      // (w0,w1)(w2,w3)
            ffma2(acc[0][0], a01.x, w.x); ffma2(acc[0][1], a01.x, w.y);
            ffma2(acc[1][0], a01.y, w.x); ffma2(acc[1][1], a01.y, w.y);
            ffma2(acc[2][0], a23.x, w.x); ffma2(acc[2][1], a23.x, w.y);
            ffma2(acc[3][0], a23.y, w.x); ffma2(acc[3][1], a23.y, w.y);
        }
        __syncthreads();
    }

    const int n = n0 + tx * 4;
    float b0 = bias[n + 0], b1 = bias[n + 1], b2 = bias[n + 2], b3 = bias[n + 3];
    #pragma unroll
    for (int i = 0; i < 4; i++) {
        int m = m0 + ty * 4 + i;
        float x0, x1, x2, x3;
        unpack2(acc[i][0], x0, x1);
        unpack2(acc[i][1], x2, x3);
        float4 o = make_float4(x0 + b0, x1 + b1, x2 + b2, x3 + b3);
        *reinterpret_cast<float4*>(&C[(size_t)m * DM + n]) = o;
    }
}

// =====================================================================
// Flash attention, fp32, packed f32x2 math.
// Grid: (S/64, B*H). Block 256 = 16x16 threads, 4x4 per thread.
// Smem (dynamic, 96KB):
//   Qs[64][128] : [k][2r] duplicated, pre-scaled by 1/sqrt(Dh)
//   Ks[64][64]  : [k][c]
//   Vs[64][64]  : [kv][c]
//   Ps[64][128] : [r][2kv] duplicated exp(scores)
// =====================================================================
__global__ void __launch_bounds__(256) attn_kernel(
    const float* __restrict__ Q, const float* __restrict__ K,
    const float* __restrict__ V, float* __restrict__ O)
{
    extern __shared__ __align__(16) float sm[];
    float (*Qs)[128] = reinterpret_cast<float(*)[128]>(sm);
    float (*Ks)[64]  = reinterpret_cast<float(*)[64]>(sm + 64 * 128);
    float (*Vs)[64]  = reinterpret_cast<float(*)[64]>(sm + 64 * 128 + 64 * 64);
    float (*Ps)[128] = reinterpret_cast<float(*)[128]>(sm + 64 * 128 + 2 * 64 * 64);

    const int tid = threadIdx.x;
    const int tx = tid & 15, ty = tid >> 4;
    const int bh = blockIdx.y;
    const int b = bh >> 3, h = bh & 7;
    const int q0 = blockIdx.x * 64;

    const float* Qb = Q + (size_t)b * S_LEN * DM + (size_t)h * DH;
    const float* Kb = K + (size_t)b * S_LEN * DM + (size_t)h * DH;
    const float* Vb = V + (size_t)b * S_LEN * DM + (size_t)h * DH;

    const float qscale = 0.125f;  // 1/sqrt(64)

    // stage Q (scaled + duplicated)
    #pragma unroll
    for (int e = tid; e < 1024; e += 256) {
        int r = e >> 4, k4 = (e & 15) << 2;
        float4 v = *reinterpret_cast<const float4*>(&Qb[(size_t)(q0 + r) * DM + k4]);
        float a = v.x * qscale, c = v.y * qscale, d = v.z * qscale, f = v.w * qscale;
        Qs[k4 + 0][2 * r] = a; Qs[k4 + 0][2 * r + 1] = a;
        Qs[k4 + 1][2 * r] = c; Qs[k4 + 1][2 * r + 1] = c;
        Qs[k4 + 2][2 * r] = d; Qs[k4 + 2][2 * r + 1] = d;
        Qs[k4 + 3][2 * r] = f; Qs[k4 + 3][2 * r + 1] = f;
    }

    float m_run[4], l_run[4];
    ull o2[4][2];
    #pragma unroll
    for (int i = 0; i < 4; i++) {
        m_run[i] = -3.0e38f; l_run[i] = 0.0f;
        o2[i][0] = 0ull; o2[i][1] = 0ull;
    }

    for (int kt = 0; kt < S_LEN / 64; kt++) {
        __syncthreads();  // prior GEMM2 done with Vs/Ps; prior GEMM1 done with Ks
        #pragma unroll
        for (int e = tid; e < 1024; e += 256) {
            int c = e >> 4, k4 = (e & 15) << 2;
            float4 v = *reinterpret_cast<const float4*>(&Kb[(size_t)(kt * 64 + c) * DM + k4]);
            Ks[k4 + 0][c] = v.x; Ks[k4 + 1][c] = v.y;
            Ks[k4 + 2][c] = v.z; Ks[k4 + 3][c] = v.w;
        }
        #pragma unroll
        for (int e = tid; e < 1024; e += 256) {
            int kv = e >> 4, c4 = (e & 15) << 2;
            *reinterpret_cast<float4*>(&Vs[kv][c4]) =
                *reinterpret_cast<const float4*>(&Vb[(size_t)(kt * 64 + kv) * DM + c4]);
        }
        __syncthreads();

        // ---- S = (Q*scale) @ K^T : packed over key columns ----
        ull s2[4][2];
        #pragma unroll
        for (int i = 0; i < 4; i++) { s2[i][0] = 0ull; s2[i][1] = 0ull; }
        #pragma unroll 8
        for (int k = 0; k < 64; k++) {
            ulonglong2 qa = *reinterpret_cast<const ulonglong2*>(&Qs[k][ty * 8]);
            ulonglong2 qb = *reinterpret_cast<const ulonglong2*>(&Qs[k][ty * 8 + 4]);
            ulonglong2 kk = *reinterpret_cast<const ulonglong2*>(&Ks[k][tx * 4]);
            ffma2(s2[0][0], qa.x, kk.x); ffma2(s2[0][1], qa.x, kk.y);
            ffma2(s2[1][0], qa.y, kk.x); ffma2(s2[1][1], qa.y, kk.y);
            ffma2(s2[2][0], qb.x, kk.x); ffma2(s2[2][1], qb.x, kk.y);
            ffma2(s2[3][0], qb.y, kk.x); ffma2(s2[3][1], qb.y, kk.y);
        }

        // ---- online softmax (row group = 16 lanes sharing ty) ----
        #pragma unroll
        for (int i = 0; i < 4; i++) {
            float v0, v1, v2, v3;
            unpack2(s2[i][0], v0, v1);
            unpack2(s2[i][1], v2, v3);
            float mt = fmaxf(fmaxf(v0, v1), fmaxf(v2, v3));
            #pragma unroll
            for (int off = 1; off < 16; off <<= 1)
                mt = fmaxf(mt, __shfl_xor_sync(0xffffffffu, mt, off));
            float mn = fmaxf(m_run[i], mt);
            float corr = __expf(m_run[i] - mn);
            float p0 = __expf(v0 - mn), p1 = __expf(v1 - mn);
            float p2 = __expf(v2 - mn), p3 = __expf(v3 - mn);
            float rs = (p0 + p1) + (p2 + p3);
            #pragma unroll
            for (int off = 1; off < 16; off <<= 1)
                rs += __shfl_xor_sync(0xffffffffu, rs, off);
            l_run[i] = l_run[i] * corr + rs;
            m_run[i] = mn;
            ull cc = pack2(corr, corr);
            o2[i][0] = fmul2(o2[i][0], cc);
            o2[i][1] = fmul2(o2[i][1], cc);
            int r = ty * 4 + i;
            *reinterpret_cast<ull*>(&Ps[r][2 * (tx * 4 + 0)]) = pack2(p0, p0);
            *reinterpret_cast<ull*>(&Ps[r][2 * (tx * 4 + 1)]) = pack2(p1, p1);
            *reinterpret_cast<ull*>(&Ps[r][2 * (tx * 4 + 2)]) = pack2(p2, p2);
            *reinterpret_cast<ull*>(&Ps[r][2 * (tx * 4 + 3)]) = pack2(p3, p3);
        }
        __syncthreads();

        // ---- O += P @ V ----
        #pragma unroll 8
        for (int kv = 0; kv < 64; kv++) {
            ulonglong2 vv = *reinterpret_cast<const ulonglong2*>(&Vs[kv][tx * 4]);
            #pragma unroll
            for (int i = 0; i < 4; i++) {
                ull p = *reinterpret_cast<const ull*>(&Ps[ty * 4 + i][2 * kv]);
                ffma2(o2[i][0], p, vv.x);
                ffma2(o2[i][1], p, vv.y);
            }
        }
    }

    // epilogue: normalize, write back to [B,S,D] with head offset (free transpose)
    float* Ob = O + (size_t)b * S_LEN * DM + (size_t)h * DH;
    #pragma unroll
    for (int i = 0; i < 4; i++) {
        float inv = 1.0f / l_run[i];
        float x0, x1, x2, x3;
        unpack2(o2[i][0], x0, x1);
        unpack2(o2[i][1], x2, x3);
        float4 o = make_float4(x0 * inv, x1 * inv, x2 * inv, x3 * inv);
        *reinterpret_cast<float4*>(&Ob[(size_t)(q0 + ty * 4 + i) * DM + tx * 4]) = o;
    }
}

// =====================================================================
extern "C" void kernel_launch(void* const* d_in, const int* in_sizes, int n_in,
                              void* d_out, int out_size)
{
    const float* q  = (const float*)d_in[0];
    const float* k  = (const float*)d_in[1];
    const float* v  = (const float*)d_in[2];
    const float* Wq = (const float*)d_in[3];
    const float* bq = (const float*)d_in[4];
    const float* Wk = (const float*)d_in[5];
    const float* bk = (const float*)d_in[6];
    const float* Wv = (const float*)d_in[7];
    const float* bv = (const float*)d_in[8];
    const float* Wo = (const float*)d_in[9];
    const float* bo = (const float*)d_in[10];
    float* out = (float*)d_out;

    float *gq, *gk, *gv, *gctx;
    cudaGetSymbolAddress((void**)&gq, g_q);
    cudaGetSymbolAddress((void**)&gk, g_k);
    cudaGetSymbolAddress((void**)&gv, g_v);
    cudaGetSymbolAddress((void**)&gctx, g_ctx);

    const int ATTN_SMEM = (64 * 128 + 2 * 64 * 64 + 64 * 128) * 4;  // 96 KB
    cudaFuncSetAttribute(attn_kernel, cudaFuncAttributeMaxDynamicSharedMemorySize, ATTN_SMEM);

    dim3 ggrid(128, 8);   // (8192/64, 512/64)
    gemm_bias_kernel<<<ggrid, 256>>>(q, Wq, bq, gq);
    gemm_bias_kernel<<<ggrid, 256>>>(k, Wk, bk, gk);
    gemm_bias_kernel<<<ggrid, 256>>>(v, Wv, bv, gv);

    dim3 agrid(S_LEN / 64, B_SZ * HN);  // (64, 16)
    attn_kernel<<<agrid, 256, ATTN_SMEM>>>(gq, gk, gv, gctx);

    gemm_bias_kernel<<<ggrid, 256>>>(gctx, Wo, bo, out);
}

// round 2
// speedup vs baseline: 1.0016x; 1.0016x over previous
#include <cuda_runtime.h>

#define S_LEN 4096
#define B_SZ  2
#define DM    512
#define HN    8
#define DH    64

typedef unsigned long long ull;

// ---------------- packed f32x2 helpers (PTX-only on Blackwell) ----------------
__device__ __forceinline__ void ffma2(ull& d, ull a, ull b) {
    asm("fma.rn.f32x2 %0, %1, %2, %0;" : "+l"(d) : "l"(a), "l"(b));
}
__device__ __forceinline__ ull fmul2(ull a, ull b) {
    ull r; asm("mul.rn.f32x2 %0, %1, %2;" : "=l"(r) : "l"(a), "l"(b)); return r;
}
__device__ __forceinline__ ull pack2(float x, float y) {
    ull r; asm("mov.b64 %0, {%1, %2};" : "=l"(r) : "f"(x), "f"(y)); return r;
}
__device__ __forceinline__ void unpack2(ull v, float& x, float& y) {
    asm("mov.b64 {%0, %1}, %2;" : "=f"(x), "=f"(y) : "l"(v));
}

// ---------------- scratch (no cudaMalloc allowed) ----------------
__device__ float g_q[(size_t)B_SZ * S_LEN * DM];
__device__ float g_k[(size_t)B_SZ * S_LEN * DM];
__device__ float g_v[(size_t)B_SZ * S_LEN * DM];
__device__ float g_ctx[(size_t)B_SZ * S_LEN * DM];

// =====================================================================
// GEMM: C[m][n] = sum_k A[m][k] * W[n][k] + bias[n]
// M = 8192 (B*S), N = K = 512. Tile 64x64, BK=32, 256 threads, 4x4/thread
// A rows stored DUPLICATED in smem so LDS.128 yields two (a,a) f32x2 pairs.
// =====================================================================
__global__ void __launch_bounds__(256) gemm_bias_kernel(
    const float* __restrict__ A, const float* __restrict__ W,
    const float* __restrict__ bias, float* __restrict__ C)
{
    __shared__ __align__(16) float As[32][128];  // [k][2*r] duplicated pairs
    __shared__ __align__(16) float Ws[32][64];   // [k][n]

    const int tid = threadIdx.x;
    const int tx = tid & 15, ty = tid >> 4;
    const int m0 = blockIdx.x * 64;
    const int n0 = blockIdx.y * 64;

    ull acc[4][2];
    #pragma unroll
    for (int i = 0; i < 4; i++) { acc[i][0] = 0ull; acc[i][1] = 0ull; }

    for (int k0 = 0; k0 < DM; k0 += 32) {
        #pragma unroll
        for (int e = tid; e < 512; e += 256) {
            int r = e >> 3, k4 = (e & 7) << 2;
            float4 v = *reinterpret_cast<const float4*>(&A[(size_t)(m0 + r) * DM + k0 + k4]);
            As[k4 + 0][2 * r] = v.x; As[k4 + 0][2 * r + 1] = v.x;
            As[k4 + 1][2 * r] = v.y; As[k4 + 1][2 * r + 1] = v.y;
            As[k4 + 2][2 * r] = v.z; As[k4 + 2][2 * r + 1] = v.z;
            As[k4 + 3][2 * r] = v.w; As[k4 + 3][2 * r + 1] = v.w;
        }
        #pragma unroll
        for (int e = tid; e < 512; e += 256) {
            int n = e >> 3, k4 = (e & 7) << 2;
            float4 v = *reinterpret_cast<const float4*>(&W[(size_t)(n0 + n) * DM + k0 + k4]);
            Ws[k4 + 0][n] = v.x; Ws[k4 + 1][n] = v.y;
            Ws[k4 + 2][n] = v.z; Ws[k4 + 3][n] = v.w;
        }
        __syncthreads();
        #pragma unroll 8
        for (int k = 0; k < 32; k++) {
            ulonglong2 a01 = *reinterpret_cast<const ulonglong2*>(&As[k][ty * 8]);      // (r0,r0)(r1,r1)
            ulonglong2 a23 = *reinterpret_cast<const ulonglong2*>(&As[k][ty * 8 + 4]);  // (r2,r2)(r3,r3)
            ulonglong2 w   = *reinterpret_cast<const ulonglong2*>(&Ws[k][tx * 4]);      // (w0,w1)(w2,w3)
            ffma2(acc[0][0], a01.x, w.x); ffma2(acc[0][1], a01.x, w.y);
            ffma2(acc[1][0], a01.y, w.x); ffma2(acc[1][1], a01.y, w.y);
            ffma2(acc[2][0], a23.x, w.x); ffma2(acc[2][1], a23.x, w.y);
            ffma2(acc[3][0], a23.y, w.x); ffma2(acc[3][1], a23.y, w.y);
        }
        __syncthreads();
    }

    const int n = n0 + tx * 4;
    float b0 = bias[n + 0], b1 = bias[n + 1], b2 = bias[n + 2], b3 = bias[n + 3];
    #pragma unroll
    for (int i = 0; i < 4; i++) {
        int m = m0 + ty * 4 + i;
        float x0, x1, x2, x3;
        unpack2(acc[i][0], x0, x1);
        unpack2(acc[i][1], x2, x3);
        float4 o = make_float4(x0 + b0, x1 + b1, x2 + b2, x3 + b3);
        *reinterpret_cast<float4*>(&C[(size_t)m * DM + n]) = o;
    }
}

// =====================================================================
// Flash attention, fp32, packed f32x2 math.
// Grid: (S/64, B*H). Block 256 = 16x16 threads, 4x4 per thread.
// Smem (dynamic, 96KB):
//   Qs[64][128] : [k][2r] duplicated, pre-scaled by 1/sqrt(Dh)
//   Ks[64][64]  : [k][c]
//   Vs[64][64]  : [kv][c]
//   Ps[64][128] : [r][2kv] duplicated exp(scores)
// =====================================================================
__global__ void __launch_bounds__(256) attn_kernel(
    const float* __restrict__ Q, const float* __restrict__ K,
    const float* __restrict__ V, float* __restrict__ O)
{
    extern __shared__ __align__(16) float sm[];
    float (*Qs)[128] = reinterpret_cast<float(*)[128]>(sm);
    float (*Ks)[64]  = reinterpret_cast<float(*)[64]>(sm + 64 * 128);
    float (*Vs)[64]  = reinterpret_cast<float(*)[64]>(sm + 64 * 128 + 64 * 64);
    float (*Ps)[128] = reinterpret_cast<float(*)[128]>(sm + 64 * 128 + 2 * 64 * 64);

    const int tid = threadIdx.x;
    const int tx = tid & 15, ty = tid >> 4;
    const int bh = blockIdx.y;
    const int b = bh >> 3, h = bh & 7;
    const int q0 = blockIdx.x * 64;

    const float* Qb = Q + (size_t)b * S_LEN * DM + (size_t)h * DH;
    const float* Kb = K + (size_t)b * S_LEN * DM + (size_t)h * DH;
    const float* Vb = V + (size_t)b * S_LEN * DM + (size_t)h * DH;

    const float qscale = 0.125f;  // 1/sqrt(64)

    // stage Q (scaled + duplicated)
    #pragma unroll
    for (int e = tid; e < 1024; e += 256) {
        int r = e >> 4, k4 = (e & 15) << 2;
        float4 v = *reinterpret_cast<const float4*>(&Qb[(size_t)(q0 + r) * DM + k4]);
        float a = v.x * qscale, c = v.y * qscale, d = v.z * qscale, f = v.w * qscale;
        Qs[k4 + 0][2 * r] = a; Qs[k4 + 0][2 * r + 1] = a;
        Qs[k4 + 1][2 * r] = c; Qs[k4 + 1][2 * r + 1] = c;
        Qs[k4 + 2][2 * r] = d; Qs[k4 + 2][2 * r + 1] = d;
        Qs[k4 + 3][2 * r] = f; Qs[k4 + 3][2 * r + 1] = f;
    }

    float m_run[4], l_run[4];
    ull o2[4][2];
    #pragma unroll
    for (int i = 0; i < 4; i++) {
        m_run[i] = -3.0e38f; l_run[i] = 0.0f;
        o2[i][0] = 0ull; o2[i][1] = 0ull;
    }

    for (int kt = 0; kt < S_LEN / 64; kt++) {
        __syncthreads();  // prior GEMM2 done with Vs/Ps; prior GEMM1 done with Ks
        #pragma unroll
        for (int e = tid; e < 1024; e += 256) {
            int c = e >> 4, k4 = (e & 15) << 2;
            float4 v = *reinterpret_cast<const float4*>(&Kb[(size_t)(kt * 64 + c) * DM + k4]);
            Ks[k4 + 0][c] = v.x; Ks[k4 + 1][c] = v.y;
            Ks[k4 + 2][c] = v.z; Ks[k4 + 3][c] = v.w;
        }
        #pragma unroll
        for (int e = tid; e < 1024; e += 256) {
            int kv = e >> 4, c4 = (e & 15) << 2;
            *reinterpret_cast<float4*>(&Vs[kv][c4]) =
                *reinterpret_cast<const float4*>(&Vb[(size_t)(kt * 64 + kv) * DM + c4]);
        }
        __syncthreads();

        // ---- S = (Q*scale) @ K^T : packed over key columns ----
        ull s2[4][2];
        #pragma unroll
        for (int i = 0; i < 4; i++) { s2[i][0] = 0ull; s2[i][1] = 0ull; }
        #pragma unroll 8
        for (int k = 0; k < 64; k++) {
            ulonglong2 qa = *reinterpret_cast<const ulonglong2*>(&Qs[k][ty * 8]);
            ulonglong2 qb = *reinterpret_cast<const ulonglong2*>(&Qs[k][ty * 8 + 4]);
            ulonglong2 kk = *reinterpret_cast<const ulonglong2*>(&Ks[k][tx * 4]);
            ffma2(s2[0][0], qa.x, kk.x); ffma2(s2[0][1], qa.x, kk.y);
            ffma2(s2[1][0], qa.y, kk.x); ffma2(s2[1][1], qa.y, kk.y);
            ffma2(s2[2][0], qb.x, kk.x); ffma2(s2[2][1], qb.x, kk.y);
            ffma2(s2[3][0], qb.y, kk.x); ffma2(s2[3][1], qb.y, kk.y);
        }

        // ---- online softmax (row group = 16 lanes sharing ty) ----
        #pragma unroll
        for (int i = 0; i < 4; i++) {
            float v0, v1, v2, v3;
            unpack2(s2[i][0], v0, v1);
            unpack2(s2[i][1], v2, v3);
            float mt = fmaxf(fmaxf(v0, v1), fmaxf(v2, v3));
            #pragma unroll
            for (int off = 1; off < 16; off <<= 1)
                mt = fmaxf(mt, __shfl_xor_sync(0xffffffffu, mt, off));
            float mn = fmaxf(m_run[i], mt);
            float corr = __expf(m_run[i] - mn);
            float p0 = __expf(v0 - mn), p1 = __expf(v1 - mn);
            float p2 = __expf(v2 - mn), p3 = __expf(v3 - mn);
            float rs = (p0 + p1) + (p2 + p3);
            #pragma unroll
            for (int off = 1; off < 16; off <<= 1)
                rs += __shfl_xor_sync(0xffffffffu, rs, off);
            l_run[i] = l_run[i] * corr + rs;
            m_run[i] = mn;
            ull cc = pack2(corr, corr);
            o2[i][0] = fmul2(o2[i][0], cc);
            o2[i][1] = fmul2(o2[i][1], cc);
            int r = ty * 4 + i;
            *reinterpret_cast<ull*>(&Ps[r][2 * (tx * 4 + 0)]) = pack2(p0, p0);
            *reinterpret_cast<ull*>(&Ps[r][2 * (tx * 4 + 1)]) = pack2(p1, p1);
            *reinterpret_cast<ull*>(&Ps[r][2 * (tx * 4 + 2)]) = pack2(p2, p2);
            *reinterpret_cast<ull*>(&Ps[r][2 * (tx * 4 + 3)]) = pack2(p3, p3);
        }
        __syncthreads();

        // ---- O += P @ V ----
        #pragma unroll 8
        for (int kv = 0; kv < 64; kv++) {
            ulonglong2 vv = *reinterpret_cast<const ulonglong2*>(&Vs[kv][tx * 4]);
            #pragma unroll
            for (int i = 0; i < 4; i++) {
                ull p = *reinterpret_cast<const ull*>(&Ps[ty * 4 + i][2 * kv]);
                ffma2(o2[i][0], p, vv.x);
                ffma2(o2[i][1], p, vv.y);
            }
        }
    }

    // epilogue: normalize, write back to [B,S,D] with head offset (free transpose)
    float* Ob = O + (size_t)b * S_LEN * DM + (size_t)h * DH;
    #pragma unroll
    for (int i = 0; i < 4; i++) {
        float inv = 1.0f / l_run[i];
        float x0, x1, x2, x3;
        unpack2(o2[i][0], x0, x1);
        unpack2(o2[i][1], x2, x3);
        float4 o = make_float4(x0 * inv, x1 * inv, x2 * inv, x3 * inv);
        *reinterpret_cast<float4*>(&Ob[(size_t)(q0 + ty * 4 + i) * DM + tx * 4]) = o;
    }
}

// =====================================================================
extern "C" void kernel_launch(void* const* d_in, const int* in_sizes, int n_in,
                              void* d_out, int out_size)
{
    const float* q  = (const float*)d_in[0];
    const float* k  = (const float*)d_in[1];
    const float* v  = (const float*)d_in[2];
    const float* Wq = (const float*)d_in[3];
    const float* bq = (const float*)d_in[4];
    const float* Wk = (const float*)d_in[5];
    const float* bk = (const float*)d_in[6];
    const float* Wv = (const float*)d_in[7];
    const float* bv = (const float*)d_in[8];
    const float* Wo = (const float*)d_in[9];
    const float* bo = (const float*)d_in[10];
    float* out = (float*)d_out;

    float *gq, *gk, *gv, *gctx;
    cudaGetSymbolAddress((void**)&gq, g_q);
    cudaGetSymbolAddress((void**)&gk, g_k);
    cudaGetSymbolAddress((void**)&gv, g_v);
    cudaGetSymbolAddress((void**)&gctx, g_ctx);

    const int ATTN_SMEM = (64 * 128 + 2 * 64 * 64 + 64 * 128) * 4;  // 96 KB
    cudaFuncSetAttribute(attn_kernel, cudaFuncAttributeMaxDynamicSharedMemorySize, ATTN_SMEM);

    dim3 ggrid(128, 8);   // (8192/64, 512/64)
    gemm_bias_kernel<<<ggrid, 256>>>(q, Wq, bq, gq);
    gemm_bias_kernel<<<ggrid, 256>>>(k, Wk, bk, gk);
    gemm_bias_kernel<<<ggrid, 256>>>(v, Wv, bv, gv);

    dim3 agrid(S_LEN / 64, B_SZ * HN);  // (64, 16)
    attn_kernel<<<agrid, 256, ATTN_SMEM>>>(gq, gk, gv, gctx);

    gemm_bias_kernel<<<ggrid, 256>>>(gctx, Wo, bo, out);
}